// round 15
// baseline (speedup 1.0000x reference)
#include <cuda_runtime.h>
#include <cstdint>

#define B_    64
#define S_    2048
#define H_    1024
#define SPLIT 16
#define CHUNK (S_ / SPLIT)      // 128 timesteps per CTA
#define TILE  4
#define NTILES (CHUNK / TILE)   // 32
#define THREADS 256             // one float4 column slice per thread
#define WARPS (THREADS / 32)

// Scratch (allocation-free: __device__ globals)
__device__ float g_expE [B_ * S_];             // exp(tanh(score)) per (b,s)
__device__ float g_partL[B_ * SPLIT];          // partial sum of exp per chunk
__device__ float g_partC[B_ * SPLIT * H_];     // partial context per chunk (4 MiB)
__device__ int   g_count[B_];                  // arrival counter per batch

__device__ __forceinline__ float tanh_approx(float v) {
    float r;
    asm("tanh.approx.f32 %0, %1;" : "=f"(r) : "f"(v));
    return r;
}

// ---------------------------------------------------------------------------
// Fused kernel, software-pipelined (R14 base + de-burst load issuance):
//  - prefetch of the next tile is SPLIT IN TWO: rows 0-1 issue before the
//    dot/reduce, rows 2-3 issue after the barrier (during finish/broadcast).
//    Same registers and same MLP over the tile period, but the L1tex queue
//    burst is halved and load issuance is spread across the whole tile,
//    reducing cross-CTA queue contention (B300 spread model: spr grows with
//    consecutive front-batched LDGs).
//  - interleaved 4-row warp reduce (9 SHFL), tanh.approx.f32, __ldcs for x,
//    __stcg/__ldcg for scratch, __stcs for outputs.
// Thread t owns H columns [4t,4t+4). tanh in [-1,1] -> softmax needs no max.
// Epilogue: threadfence-reduction; 16th CTA per batch finishes context +
// weights (deterministic, graph-replayable; counter reset by finisher).
// ---------------------------------------------------------------------------
__global__ __launch_bounds__(THREADS, 4)
void fused_kernel(const float* __restrict__ x,
                  const float* __restrict__ w,
                  const float* __restrict__ bptr,
                  float* __restrict__ ctx_out,
                  float* __restrict__ wts_out)
{
    __shared__ float red[2][WARPS * TILE];   // ping-pong per-warp dot partials
    __shared__ float lred[TILE];
    __shared__ int   s_last;
    __shared__ float s_inv;

    const int b     = blockIdx.x / SPLIT;
    const int chunk = blockIdx.x % SPLIT;
    const int tid   = threadIdx.x;
    const int warp  = tid >> 5;
    const int lane  = tid & 31;
    const float bias = __ldg(bptr);
    const float4 w4 = reinterpret_cast<const float4*>(w)[tid];

    float4 acc = make_float4(0.f, 0.f, 0.f, 0.f);
    float lsum = 0.f;                        // warp 0, lanes 0-3 accumulate

    const int s0 = chunk * CHUNK;
    const float4* xp0 = reinterpret_cast<const float4*>(x) +
                        ((size_t)b * S_ + s0) * (H_ / 4) + tid;

    float4 xa[TILE], xb[TILE];

    // preload tile 0 into xa (streaming)
    #pragma unroll
    for (int s = 0; s < TILE; s++)
        xa[s] = __ldcs(&xp0[(size_t)s * (H_ / 4)]);

    // one pipelined tile step: consume cur[], prefetch tile nt into nxt[]
    // (prefetch split: rows 0-1 before the reduce, rows 2-3 after the barrier)
    auto step = [&](int tile, float4* cur, float4* nxt) {
        const int p = tile & 1;

        // next tile (clamped: last tile re-loads itself, in-bounds)
        const int nt = (tile + 1 < NTILES) ? tile + 1 : NTILES - 1;
        const float4* xpn = xp0 + (size_t)nt * TILE * (H_ / 4);

        // prefetch first half of next tile
        nxt[0] = __ldcs(&xpn[(size_t)0 * (H_ / 4)]);
        nxt[1] = __ldcs(&xpn[(size_t)1 * (H_ / 4)]);

        // dots from current buffer
        float d[TILE];
        #pragma unroll
        for (int s = 0; s < TILE; s++)
            d[s] = cur[s].x * w4.x + cur[s].y * w4.y
                 + cur[s].z * w4.z + cur[s].w * w4.w;

        // interleaved 4-row warp reduce: 9 SHFL total.
        #pragma unroll
        for (int s = 0; s < TILE; s++)
            d[s] += __shfl_xor_sync(0xffffffffu, d[s], 1);
        float e0 = (lane & 1) ? d[1] : d[0];
        float e1 = (lane & 1) ? d[3] : d[2];
        e0 += __shfl_xor_sync(0xffffffffu, e0, 2);
        e1 += __shfl_xor_sync(0xffffffffu, e1, 2);
        float f = (lane & 2) ? e1 : e0;
        f += __shfl_xor_sync(0xffffffffu, f, 4);
        f += __shfl_xor_sync(0xffffffffu, f, 8);
        f += __shfl_xor_sync(0xffffffffu, f, 16);
        // lane L (< 4) holds the full warp sum of row (L & 3)
        if (lane < TILE)
            red[p][warp * TILE + lane] = f;

        __syncthreads();                      // single barrier per tile

        // prefetch second half of next tile (spreads load issuance)
        nxt[2] = __ldcs(&xpn[(size_t)2 * (H_ / 4)]);
        nxt[3] = __ldcs(&xpn[(size_t)3 * (H_ / 4)]);

        // redundant finish in every warp: lanes 0-3 own one timestep each
        float t = 0.f;
        if (lane < TILE) {
            float v = 0.f;
            #pragma unroll
            for (int j = 0; j < WARPS; j++)
                v += red[p][j * TILE + lane];
            t = __expf(tanh_approx(v + bias));
            if (warp == 0) {
                __stcg(&g_expE[(size_t)b * S_ + s0 + tile * TILE + lane], t);
                lsum += t;
            }
        }

        // broadcast t and accumulate from the current register buffer
        #pragma unroll
        for (int s = 0; s < TILE; s++) {
            const float ts = __shfl_sync(0xffffffffu, t, s);
            acc.x += ts * cur[s].x;
            acc.y += ts * cur[s].y;
            acc.z += ts * cur[s].z;
            acc.w += ts * cur[s].w;
        }
    };

    #pragma unroll 1
    for (int t2 = 0; t2 < NTILES; t2 += 2) {
        step(t2,     xa, xb);
        step(t2 + 1, xb, xa);
    }

    // flush partial context (L2-only: consumer is a different CTA)
    __stcg(&reinterpret_cast<float4*>(
               g_partC + ((size_t)b * SPLIT + chunk) * H_)[tid], acc);

    // combine warp-0 lane lsums -> partL
    if (warp == 0 && lane < TILE) lred[lane] = lsum;
    __syncthreads();
    if (tid == 0) {
        float l = 0.f;
        #pragma unroll
        for (int i = 0; i < TILE; i++) l += lred[i];
        __stcg(&g_partL[b * SPLIT + chunk], l);
    }

    // -------- finisher election (threadfence reduction pattern) --------
    __threadfence();
    __syncthreads();
    if (tid == 0) {
        const int old = atomicAdd(&g_count[b], 1);
        s_last = (old == SPLIT - 1);
        if (s_last) g_count[b] = 0;   // reset for next replay (all arrived)
    }
    __syncthreads();
    if (!s_last) return;
    __threadfence();                  // acquire: see peers' flushes

    // -------- epilogue: this CTA finishes batch b --------
    if (tid < 32) {
        float l = (tid < SPLIT) ? __ldcg(&g_partL[b * SPLIT + tid]) : 0.f;
        #pragma unroll
        for (int off = 16; off; off >>= 1)
            l += __shfl_xor_sync(0xffffffffu, l, off);
        if (tid == 0) s_inv = 1.f / l;
    }
    __syncthreads();
    const float inv = s_inv;

    // context[b][:] : 256 threads x one float4, 16 independent partial loads
    float4 c = make_float4(0.f, 0.f, 0.f, 0.f);
    #pragma unroll
    for (int cc = 0; cc < SPLIT; cc++) {
        float4 v = __ldcg(&reinterpret_cast<const float4*>(
            g_partC + ((size_t)b * SPLIT + cc) * H_)[tid]);
        c.x += v.x; c.y += v.y; c.z += v.z; c.w += v.w;
    }
    c.x *= inv; c.y *= inv; c.z *= inv; c.w *= inv;
    __stcs(&reinterpret_cast<float4*>(ctx_out)[b * (H_ / 4) + tid], c);

    // weights[b][:] : S/4 = 512 float4, 2 per thread
    #pragma unroll
    for (int i = 0; i < S_ / 4 / THREADS; i++) {
        const int idx = b * (S_ / 4) + i * THREADS + tid;
        float4 e = __ldcg(&reinterpret_cast<const float4*>(g_expE)[idx]);
        e.x *= inv; e.y *= inv; e.z *= inv; e.w *= inv;
        __stcs(&reinterpret_cast<float4*>(wts_out)[idx], e);
    }
}

extern "C" void kernel_launch(void* const* d_in, const int* in_sizes, int n_in,
                              void* d_out, int out_size)
{
    const float* x    = (const float*)d_in[0];   // rnn_output [B,S,H]
    const float* w    = (const float*)d_in[1];   // attn_w [H]
    const float* bptr = (const float*)d_in[2];   // attn_b scalar

    float* out = (float*)d_out;                  // context [B,H] then weights [B,S]
    float* ctx_out = out;
    float* wts_out = out + (size_t)B_ * H_;

    fused_kernel<<<B_ * SPLIT, THREADS>>>(x, w, bptr, ctx_out, wts_out);
}

// round 16
// speedup vs baseline: 1.0550x; 1.0550x over previous
#include <cuda_runtime.h>
#include <cstdint>

#define B_    64
#define S_    2048
#define H_    1024
#define SPLIT 16
#define CHUNK (S_ / SPLIT)      // 128 timesteps per CTA
#define TILE  8
#define NTILES (CHUNK / TILE)   // 16
#define THREADS 256             // one float4 column slice per thread
#define WARPS (THREADS / 32)

// Scratch (allocation-free: __device__ globals)
__device__ float g_expE [B_ * S_];             // exp(tanh(score)) per (b,s)
__device__ float g_partL[B_ * SPLIT];          // partial sum of exp per chunk
__device__ float g_partC[B_ * SPLIT * H_];     // partial context per chunk (4 MiB)
__device__ int   g_count[B_];                  // arrival counter per batch

__device__ __forceinline__ float tanh_approx(float v) {
    float r;
    asm("tanh.approx.f32 %0, %1;" : "=f"(r) : "f"(v));
    return r;
}

// ---------------------------------------------------------------------------
// Fused kernel: R7 structure (TILE=8 front-batched loads, MLP=8 -> best
// measured DRAM duty) + R14 micro-opts (short reduce, tanh.approx, cache
// hints) + R9 fused finisher epilogue.
// Thread t owns H columns [4t,4t+4). Per tile of 8 timesteps:
//   1. 8 front-batched float4 loads (__ldcs: single-use streaming)
//   2. 8 partial dots vs w4
//   3. interleaved 8-row warp reduce: 16 SHFL (vs 40 naive); lane L ends
//      holding the FULL warp sum of row (L&7)
//   4. lanes 0-7 publish to ping-pong red[p]; ONE __syncthreads
//   5. every warp redundantly finishes: lanes 0-7 sum 8 per-warp values,
//      t = __expf(tanh.approx(v + bias))   (tanh in [-1,1] -> no max sub)
//   6. shuffle-broadcast t, acc += t*xr from registers
// Epilogue: threadfence-reduction; 16th CTA per batch reduces partials,
// writes context + weights (deterministic; counter reset by finisher).
// ---------------------------------------------------------------------------
__global__ __launch_bounds__(THREADS, 4)
void fused_kernel(const float* __restrict__ x,
                  const float* __restrict__ w,
                  const float* __restrict__ bptr,
                  float* __restrict__ ctx_out,
                  float* __restrict__ wts_out)
{
    __shared__ float red[2][WARPS * TILE];   // ping-pong per-warp dot partials
    __shared__ int   s_last;
    __shared__ float s_inv;

    const int b     = blockIdx.x / SPLIT;
    const int chunk = blockIdx.x % SPLIT;
    const int tid   = threadIdx.x;
    const int warp  = tid >> 5;
    const int lane  = tid & 31;
    const float bias = __ldg(bptr);
    const float4 w4 = reinterpret_cast<const float4*>(w)[tid];

    float4 acc = make_float4(0.f, 0.f, 0.f, 0.f);
    float lsum = 0.f;                        // warp 0, lanes 0-7 accumulate

    const int s0 = chunk * CHUNK;
    const float4* xp0 = reinterpret_cast<const float4*>(x) +
                        ((size_t)b * S_ + s0) * (H_ / 4) + tid;

    #pragma unroll 1
    for (int tile = 0; tile < NTILES; tile++) {
        const float4* xp = xp0 + (size_t)tile * TILE * (H_ / 4);
        const int p = tile & 1;

        // 1. front-batched streaming loads (MLP=8)
        float4 xr[TILE];
        #pragma unroll
        for (int s = 0; s < TILE; s++)
            xr[s] = __ldcs(&xp[(size_t)s * (H_ / 4)]);

        // 2. partial dots
        float d[TILE];
        #pragma unroll
        for (int s = 0; s < TILE; s++)
            d[s] = xr[s].x * w4.x + xr[s].y * w4.y
                 + xr[s].z * w4.z + xr[s].w * w4.w;

        // 3. interleaved 8-row warp reduce: 16 SHFL total.
        #pragma unroll
        for (int s = 0; s < TILE; s++)
            d[s] += __shfl_xor_sync(0xffffffffu, d[s], 1);
        // fold by lane bit0 -> 4 live values
        float e0 = (lane & 1) ? d[1] : d[0];
        float e1 = (lane & 1) ? d[3] : d[2];
        float e2 = (lane & 1) ? d[5] : d[4];
        float e3 = (lane & 1) ? d[7] : d[6];
        e0 += __shfl_xor_sync(0xffffffffu, e0, 2);
        e1 += __shfl_xor_sync(0xffffffffu, e1, 2);
        e2 += __shfl_xor_sync(0xffffffffu, e2, 2);
        e3 += __shfl_xor_sync(0xffffffffu, e3, 2);
        // fold by lane bit1 -> 2 live values
        float f0 = (lane & 2) ? e1 : e0;
        float f1 = (lane & 2) ? e3 : e2;
        f0 += __shfl_xor_sync(0xffffffffu, f0, 4);
        f1 += __shfl_xor_sync(0xffffffffu, f1, 4);
        // fold by lane bit2 -> 1 live value; lane L carries row (L & 7)
        float f = (lane & 4) ? f1 : f0;
        f += __shfl_xor_sync(0xffffffffu, f, 8);
        f += __shfl_xor_sync(0xffffffffu, f, 16);

        // 4. lanes 0-7 publish per-warp row sums
        if (lane < TILE)
            red[p][warp * TILE + lane] = f;

        __syncthreads();                      // single barrier per tile

        // 5. redundant finish in every warp: lanes 0-7 own one timestep each
        float t = 0.f;
        if (lane < TILE) {
            float v = 0.f;
            #pragma unroll
            for (int j = 0; j < WARPS; j++)
                v += red[p][j * TILE + lane];
            t = __expf(tanh_approx(v + bias));
            if (warp == 0) {
                __stcg(&g_expE[(size_t)b * S_ + s0 + tile * TILE + lane], t);
                lsum += t;
            }
        }

        // 6. broadcast t and accumulate from registers
        #pragma unroll
        for (int s = 0; s < TILE; s++) {
            const float ts = __shfl_sync(0xffffffffu, t, s);
            acc.x += ts * xr[s].x;
            acc.y += ts * xr[s].y;
            acc.z += ts * xr[s].z;
            acc.w += ts * xr[s].w;
        }
    }

    // flush partial context (L2-only: consumer is a different CTA)
    __stcg(&reinterpret_cast<float4*>(
               g_partC + ((size_t)b * SPLIT + chunk) * H_)[tid], acc);

    // warp 0: lanes 0-7 hold partial lsums -> reduce in-warp, lane 0 stores
    if (warp == 0) {
        lsum += __shfl_xor_sync(0xffffffffu, lsum, 1);
        lsum += __shfl_xor_sync(0xffffffffu, lsum, 2);
        lsum += __shfl_xor_sync(0xffffffffu, lsum, 4);
        if (lane == 0) __stcg(&g_partL[b * SPLIT + chunk], lsum);
    }

    // -------- finisher election (threadfence reduction pattern) --------
    __threadfence();
    __syncthreads();
    if (tid == 0) {
        const int old = atomicAdd(&g_count[b], 1);
        s_last = (old == SPLIT - 1);
        if (s_last) g_count[b] = 0;   // reset for next replay (all arrived)
    }
    __syncthreads();
    if (!s_last) return;
    __threadfence();                  // acquire: see peers' flushes

    // -------- epilogue: this CTA finishes batch b --------
    if (tid < 32) {
        float l = (tid < SPLIT) ? __ldcg(&g_partL[b * SPLIT + tid]) : 0.f;
        #pragma unroll
        for (int off = 16; off; off >>= 1)
            l += __shfl_xor_sync(0xffffffffu, l, off);
        if (tid == 0) s_inv = 1.f / l;
    }
    __syncthreads();
    const float inv = s_inv;

    // context[b][:] : 256 threads x one float4, 16 independent partial loads
    float4 c = make_float4(0.f, 0.f, 0.f, 0.f);
    #pragma unroll
    for (int cc = 0; cc < SPLIT; cc++) {
        float4 v = __ldcg(&reinterpret_cast<const float4*>(
            g_partC + ((size_t)b * SPLIT + cc) * H_)[tid]);
        c.x += v.x; c.y += v.y; c.z += v.z; c.w += v.w;
    }
    c.x *= inv; c.y *= inv; c.z *= inv; c.w *= inv;
    __stcs(&reinterpret_cast<float4*>(ctx_out)[b * (H_ / 4) + tid], c);

    // weights[b][:] : S/4 = 512 float4, 2 per thread
    #pragma unroll
    for (int i = 0; i < S_ / 4 / THREADS; i++) {
        const int idx = b * (S_ / 4) + i * THREADS + tid;
        float4 e = __ldcg(&reinterpret_cast<const float4*>(g_expE)[idx]);
        e.x *= inv; e.y *= inv; e.z *= inv; e.w *= inv;
        __stcs(&reinterpret_cast<float4*>(wts_out)[idx], e);
    }
}

extern "C" void kernel_launch(void* const* d_in, const int* in_sizes, int n_in,
                              void* d_out, int out_size)
{
    const float* x    = (const float*)d_in[0];   // rnn_output [B,S,H]
    const float* w    = (const float*)d_in[1];   // attn_w [H]
    const float* bptr = (const float*)d_in[2];   // attn_b scalar

    float* out = (float*)d_out;                  // context [B,H] then weights [B,S]
    float* ctx_out = out;
    float* wts_out = out + (size_t)B_ * H_;

    fused_kernel<<<B_ * SPLIT, THREADS>>>(x, w, bptr, ctx_out, wts_out);
}